// round 16
// baseline (speedup 1.0000x reference)
#include <cuda_runtime.h>
#include <cuda_fp16.h>
#include <math.h>
#include <stdint.h>

// ---------------------------------------------------------------------------
// ChildSumTreeLSTM, perfect binary tree N = 131071 = 2^17 - 1, dims 256/256.
//
//   Y[N,1024]   = X @ [W_ioux; W_fx]^T + folded biases          (HMMA, fp16 out)
//   per level:  Gf[2c,256]   = h_children @ W_fh^T              (HMMA, fp16 out)
//               Giou[c,768]  = (h_l + h_r) @ W_iouh^T           (HMMA, hsum)
//               combine -> c,h of parents (+ next level's hsum)
//
// Large levels (c > 1024): frozen engine — CTA 128x128, 4 warps of 64x64,
// K-chunk 64, 3-stage cp.async, one barrier per chunk, B reg double-buffer.
// Small levels (c <= 1024): warp-per-16x64 direct-LDG GEMM (no smem) to kill
// the 12us-per-level serial-CTA latency tail.
// mma.sync.m16n8k16 f16 -> fp32 accum, single-term f16 operands.
// ---------------------------------------------------------------------------

#define NN 131071

// ---------------- device scratch (no allocations allowed) ------------------
static __device__ __half g_Y[(size_t)131072 * 1024];
static __device__ __half g_Gf[(size_t)65536 * 256];
static __device__ __half g_Giou[(size_t)32768 * 768];
static __device__ float  g_c[(size_t)131072 * 256];
static __device__ __half g_h[(size_t)131072 * 256];
static __device__ __half g_hs[(size_t)65536 * 256];
static __device__ __half g_X[(size_t)131072 * 256];   // row NN stays 0
static __device__ __half g_W1[1024 * 256];
static __device__ __half g_W2[1024 * 256];
static __device__ float  g_b1[1024];

// ---------------- helpers ---------------------------------------------------
__device__ __forceinline__ float fsig(float x) {
    return __fdividef(1.0f, 1.0f + __expf(-x));
}
__device__ __forceinline__ float ftanh(float x) {
    x = fminf(fmaxf(x, -30.0f), 30.0f);
    const float e = __expf(2.0f * x);
    return __fdividef(e - 1.0f, e + 1.0f);
}

__device__ __forceinline__ uint32_t smem_u32(const void* p) {
    uint32_t a;
    asm("{ .reg .u64 t; cvta.to.shared.u64 t, %1; cvt.u32.u64 %0, t; }"
        : "=r"(a) : "l"(p));
    return a;
}

__device__ __forceinline__ void ldmatrix_x4(uint32_t* r, uint32_t addr) {
    asm volatile("ldmatrix.sync.aligned.m8n8.x4.shared.b16 {%0,%1,%2,%3}, [%4];"
                 : "=r"(r[0]), "=r"(r[1]), "=r"(r[2]), "=r"(r[3]) : "r"(addr));
}

__device__ __forceinline__ void mma16816(float* d, const uint32_t* a,
                                         uint32_t b0, uint32_t b1) {
    asm volatile(
        "mma.sync.aligned.m16n8k16.row.col.f32.f16.f16.f32 "
        "{%0,%1,%2,%3}, {%4,%5,%6,%7}, {%8,%9}, {%0,%1,%2,%3};"
        : "+f"(d[0]), "+f"(d[1]), "+f"(d[2]), "+f"(d[3])
        : "r"(a[0]), "r"(a[1]), "r"(a[2]), "r"(a[3]), "r"(b0), "r"(b1));
}

__device__ __forceinline__ void cp16(uint32_t dst, const void* src) {
    asm volatile("cp.async.cg.shared.global [%0], [%1], 16;"
                 :: "r"(dst), "l"(__cvta_generic_to_global(src)));
}
#define CP_COMMIT() asm volatile("cp.async.commit_group;" ::: "memory")
#define CP_WAIT2()  asm volatile("cp.async.wait_group 2;" ::: "memory")

__device__ __forceinline__ uint32_t pack2(float x, float y) {
    __half2 h = __floats2half2_rn(x, y);
    return *reinterpret_cast<uint32_t*>(&h);
}
__device__ __forceinline__ float4 h4f(uint2 u) {
    __half2 a = *reinterpret_cast<__half2*>(&u.x);
    __half2 b = *reinterpret_cast<__half2*>(&u.y);
    float2 f0 = __half22float2(a), f1 = __half22float2(b);
    return make_float4(f0.x, f0.y, f1.x, f1.y);
}
__device__ __forceinline__ float4 ldh4(const __half* p) {
    return h4f(*reinterpret_cast<const uint2*>(p));
}
__device__ __forceinline__ void sth4(__half* p, float a, float b, float c, float d) {
    uint2 u;
    u.x = pack2(a, b);
    u.y = pack2(c, d);
    *reinterpret_cast<uint2*>(p) = u;
}

// ---------------- GEMM tile config (large-level engine) ----------------------
#define PSTRIDE 144
#define PANEL   (128 * PSTRIDE)    // 18432
#define STAGE   (2 * PANEL)        // 36864: A | B
#define SMEM_BYTES (3 * STAGE)     // 110592 -> 2 CTAs/SM

// Pointers pre-offset to tile. Row stride A/B = 256. Padded arrays: no guards.
// C is fp16, leading dim ldc. 128 threads: 4 warps, each a 64x64 subtile.
__device__ __forceinline__ void gemm_tile(const __half* __restrict__ A,
                                          const __half* __restrict__ B,
                                          __half* __restrict__ C, int ldc,
                                          const float* __restrict__ bias) {
    extern __shared__ char smem[];
    const uint32_t sb = smem_u32(smem);
    const int tid = (int)threadIdx.x;
    const int lane = tid & 31;
    const int wid = tid >> 5;        // 0..3
    const int wm = wid & 1;          // 64-row half
    const int wn = wid >> 1;         // 64-col half

    float acc[4][8][4];
#pragma unroll
    for (int mt = 0; mt < 4; mt++)
#pragma unroll
        for (int nt = 0; nt < 8; nt++)
#pragma unroll
            for (int i = 0; i < 4; i++) acc[mt][nt][i] = 0.0f;

    const __half* srcp[2] = {A, B};

    auto issue = [&](int kc) {
        const uint32_t sbase = sb + (uint32_t)(kc % 3) * STAGE;
        const int koff = kc * 64;
#pragma unroll
        for (int it = 0; it < 16; it++) {
            const int panel = it >> 3;               // 0: A, 1: B
            const int slot = (it & 7) * 128 + tid;   // 0..1023
            const int row = slot >> 3;
            const int c16 = slot & 7;
            cp16(sbase + (uint32_t)(panel * PANEL + row * PSTRIDE + c16 * 16),
                 srcp[panel] + (size_t)row * 256 + koff + c16 * 8);
        }
        CP_COMMIT();
    };

    issue(0);
    issue(1);
    issue(2);

    const uint32_t aoff =
        (uint32_t)((wm * 64 + (lane & 15)) * PSTRIDE + (lane >> 4) * 16);
    const uint32_t boff = (uint32_t)PANEL +
        (uint32_t)((wn * 64 + (lane & 15)) * PSTRIDE + (lane >> 4) * 16);

#pragma unroll 1
    for (int kc = 0; kc < 4; kc++) {
        CP_WAIT2();
        __syncthreads();   // single barrier per chunk (3-stage ring is safe)
        const uint32_t sbase = sb + (uint32_t)(kc % 3) * STAGE;
        const uint32_t arow = sbase + aoff;
        const uint32_t brow = sbase + boff;

        // B double-buffered across ks; A loaded at use.
        uint32_t bh[2][4][4];
#pragma unroll
        for (int nq = 0; nq < 4; nq++)
            ldmatrix_x4(bh[0][nq], brow + nq * (16 * PSTRIDE));

#pragma unroll
        for (int ks = 0; ks < 4; ks++) {
            const int cur = ks & 1;
            const int nxt = cur ^ 1;
            const uint32_t kb = (uint32_t)(ks * 32);
            uint32_t ah[4][4];
#pragma unroll
            for (int mt = 0; mt < 4; mt++)
                ldmatrix_x4(ah[mt], arow + mt * (16 * PSTRIDE) + kb);
            if (ks < 3) {
#pragma unroll
                for (int nq = 0; nq < 4; nq++)
                    ldmatrix_x4(bh[nxt][nq],
                                brow + nq * (16 * PSTRIDE) + kb + 32);
            }
#pragma unroll
            for (int mt = 0; mt < 4; mt++) {
#pragma unroll
                for (int nt = 0; nt < 8; nt++) {
                    mma16816(acc[mt][nt], ah[mt],
                             bh[cur][nt >> 1][nt & 1],
                             bh[cur][nt >> 1][(nt & 1) + 2]);
                }
            }
        }
        if (kc == 0) issue(3);
        CP_COMMIT();   // empty for kc>=1: keeps wait_group 2 uniform
    }

    // ---- epilogue: fp16 C, 2 cols per 32-bit store ----
#pragma unroll
    for (int mt = 0; mt < 4; mt++) {
        const int r0 = wm * 64 + mt * 16 + (lane >> 2);
#pragma unroll
        for (int nt = 0; nt < 8; nt++) {
            const int col = wn * 64 + nt * 8 + (lane & 3) * 2;
            float b0 = 0.f, b1 = 0.f;
            if (bias) { b0 = bias[col]; b1 = bias[col + 1]; }
            *reinterpret_cast<uint32_t*>(C + (size_t)r0 * ldc + col) =
                pack2(acc[mt][nt][0] + b0, acc[mt][nt][1] + b1);
            *reinterpret_cast<uint32_t*>(C + (size_t)(r0 + 8) * ldc + col) =
                pack2(acc[mt][nt][2] + b0, acc[mt][nt][3] + b1);
        }
    }
}

// ---------------------------------------------------------------------------
// Init GEMM: single launch. Tiles 0..6143 = main slabs (1024 m x 6 n),
// tiles 6144..7167 = fx slab (first 512 m-tiles x 2 n).
__global__ void __launch_bounds__(128, 2) gemm_init_k() {
    const int bid = (int)blockIdx.x;
    size_t m0, n0;
    if (bid < 6144) {
        m0 = (size_t)(bid % 1024) * 128;
        n0 = (size_t)(bid / 1024) * 128;
    } else {
        const int r = bid - 6144;
        m0 = (size_t)(r % 512) * 128;
        n0 = (size_t)(6 + r / 512) * 128;
    }
    gemm_tile(g_X + m0 * 256, g_W1 + n0 * 256,
              g_Y + m0 * 1024 + n0, 1024, g_b1 + n0);
}

// Large-level recurrent GEMM (c > 1024): tile-parallel grid.
__global__ void __launch_bounds__(128, 2) gemm_rec_k(int cs, int start, int c) {
    const int tiles_f = (2 * c + 127) >> 7;
    const int bid = (int)blockIdx.x;
    if (bid < tiles_f * 2) {
        const size_t mt = (size_t)(bid >> 1);
        const size_t nt = (size_t)(bid & 1);
        gemm_tile(g_h + ((size_t)cs + mt * 128) * 256,
                  g_W2 + (768 + nt * 128) * 256,
                  g_Gf + mt * 128 * 256 + nt * 128, 256, nullptr);
    } else {
        const int r = bid - tiles_f * 2;
        const size_t mt = (size_t)(r / 6);
        const size_t nt = (size_t)(r % 6);
        gemm_tile(g_hs + ((size_t)start + mt * 128) * 256,
                  g_W2 + nt * 128 * 256,
                  g_Giou + mt * 128 * 768 + nt * 128, 768, nullptr);
    }
}

// ---------------------------------------------------------------------------
// Small-level recurrent GEMM (c <= 1024): one warp per 16x64 output chunk,
// full K=256, operands via direct 32-bit LDG in mma fragment layout (L2-hot).
// Padded arrays: out-of-range rows compute/store garbage into owned padding.
__global__ void __launch_bounds__(128) gemm_small_k(int cs, int start, int c) {
    const int w = ((int)blockIdx.x * 128 + (int)threadIdx.x) >> 5;
    const int lane = (int)threadIdx.x & 31;
    const int rbf = (2 * c + 15) >> 4;
    const int warps_f = rbf * 4;
    const int rbi = (c + 15) >> 4;
    const int warps_i = rbi * 12;
    if (w >= warps_f + warps_i) return;

    const __half* A;
    const __half* B;
    __half* C;
    int ldc;
    if (w < warps_f) {
        const int rb = w >> 2, cb = w & 3;
        A = g_h + ((size_t)cs + (size_t)rb * 16) * 256;
        B = g_W2 + (size_t)(768 + cb * 64) * 256;
        C = g_Gf + (size_t)rb * 16 * 256 + cb * 64;
        ldc = 256;
    } else {
        const int w2 = w - warps_f;
        const int rb = w2 / 12, cb = w2 % 12;
        A = g_hs + ((size_t)start + (size_t)rb * 16) * 256;
        B = g_W2 + (size_t)cb * 64 * 256;
        C = g_Giou + (size_t)rb * 16 * 768 + cb * 64;
        ldc = 768;
    }

    const int r = lane >> 2;          // 0..7
    const int c2 = (lane & 3) * 2;    // 0,2,4,6

    float acc[8][4];
#pragma unroll
    for (int q = 0; q < 8; q++)
#pragma unroll
        for (int i = 0; i < 4; i++) acc[q][i] = 0.0f;

#pragma unroll
    for (int ks = 0; ks < 16; ks++) {
        const int k0 = ks * 16;
        uint32_t a[4];
        a[0] = *(const uint32_t*)(A + (size_t)r * 256 + k0 + c2);
        a[1] = *(const uint32_t*)(A + (size_t)(r + 8) * 256 + k0 + c2);
        a[2] = *(const uint32_t*)(A + (size_t)r * 256 + k0 + c2 + 8);
        a[3] = *(const uint32_t*)(A + (size_t)(r + 8) * 256 + k0 + c2 + 8);
#pragma unroll
        for (int q = 0; q < 8; q++) {
            const __half* bp = B + (size_t)(q * 8 + r) * 256 + k0 + c2;
            const uint32_t b0 = *(const uint32_t*)bp;
            const uint32_t b1 = *(const uint32_t*)(bp + 8);
            mma16816(acc[q], a, b0, b1);
        }
    }

#pragma unroll
    for (int q = 0; q < 8; q++) {
        const int col = q * 8 + c2;
        *(uint32_t*)(C + (size_t)r * ldc + col) = pack2(acc[q][0], acc[q][1]);
        *(uint32_t*)(C + (size_t)(r + 8) * ldc + col) =
            pack2(acc[q][2], acc[q][3]);
    }
}

// ---------------------------------------------------------------------------
__global__ void pack_weights_k(const float* __restrict__ W_ioux,
                               const float* __restrict__ b_ioux,
                               const float* __restrict__ W_iouh,
                               const float* __restrict__ b_iouh,
                               const float* __restrict__ W_fx,
                               const float* __restrict__ b_fx,
                               const float* __restrict__ W_fh,
                               const float* __restrict__ b_fh) {
    const int i = blockIdx.x * blockDim.x + threadIdx.x;
    if (i >= 1024 * 256) return;
    const int r = i >> 8;
    const int cc = i & 255;
    const float w1 = (r < 768) ? W_ioux[i] : W_fx[(r - 768) * 256 + cc];
    const float w2 = (r < 768) ? W_iouh[i] : W_fh[(r - 768) * 256 + cc];
    g_W1[i] = __float2half_rn(w1);
    g_W2[i] = __float2half_rn(w2);
    if (cc == 0)
        g_b1[r] = (r < 768) ? (b_ioux[r] + b_iouh[r])
                            : (b_fx[r - 768] + b_fh[r - 768]);
}

__global__ void convert_x_k(const float* __restrict__ X) {
    const size_t i = ((size_t)blockIdx.x * 256 + threadIdx.x) * 4;
    if (i >= (size_t)NN * 256) return;
    const float4 v = *reinterpret_cast<const float4*>(X + i);
    sth4(g_X + i, v.x, v.y, v.z, v.w);
}

// ---------------------------------------------------------------------------
// Leaves (level 16): block = 4 sibling pairs x 64 lanes (4 elems per lane).
__global__ void leaf_k() {
    const int tid = (int)threadIdx.x;
    const int j = (int)blockIdx.x * 4 + (tid >> 6);   // pair id 0..32767
    const int d = (tid & 63) * 4;
    const int n0 = 65535 + 2 * j;
    const __half* Y0 = g_Y + (size_t)n0 * 1024;
    const __half* Y1 = Y0 + 1024;

    const float4 i0 = ldh4(Y0 + d),        i1 = ldh4(Y1 + d);
    const float4 o0 = ldh4(Y0 + 256 + d),  o1 = ldh4(Y1 + 256 + d);
    const float4 u0 = ldh4(Y0 + 512 + d),  u1 = ldh4(Y1 + 512 + d);

    float c0[4], h0[4], c1[4], h1[4];
#pragma unroll
    for (int t = 0; t < 4; t++) {
        c0[t] = fsig((&i0.x)[t]) * ftanh((&u0.x)[t]);
        h0[t] = fsig((&o0.x)[t]) * ftanh(c0[t]);
        c1[t] = fsig((&i1.x)[t]) * ftanh((&u1.x)[t]);
        h1[t] = fsig((&o1.x)[t]) * ftanh(c1[t]);
    }

    const size_t b0 = (size_t)n0 * 256 + d;
    *(float4*)(g_c + b0) = make_float4(c0[0], c0[1], c0[2], c0[3]);
    *(float4*)(g_c + b0 + 256) = make_float4(c1[0], c1[1], c1[2], c1[3]);
    sth4(g_h + b0, h0[0], h0[1], h0[2], h0[3]);
    sth4(g_h + b0 + 256, h1[0], h1[1], h1[2], h1[3]);
    sth4(g_hs + (size_t)(32767 + j) * 256 + d,
         h0[0] + h1[0], h0[1] + h1[1], h0[2] + h1[2], h0[3] + h1[3]);
}

// Internal levels lvl >= 1: block = 4 parent-pairs x 64 lanes.
__global__ void combine_k(int start, int cs, int pstart, int npairs) {
    const int tid = (int)threadIdx.x;
    const int j = (int)blockIdx.x * 4 + (tid >> 6);   // parent-pair id
    if (j >= npairs) return;
    const int d = (tid & 63) * 4;
    const int n0 = start + 2 * j;
    const __half* Y0 = g_Y + (size_t)n0 * 1024;
    const __half* Y1 = Y0 + 1024;
    const __half* Gi0 = g_Giou + (size_t)(2 * j) * 768;
    const __half* Gi1 = Gi0 + 768;
    const __half* Gf = g_Gf + (size_t)(4 * j) * 256;
    const float* cch = g_c + (size_t)(cs + 4 * j) * 256;

    float c0[4], h0[4], c1[4], h1[4];
#define ELT(Yn, Gi, GfL, GfR, CL, CR, co, ho)                                   \
    {                                                                           \
        const float4 yi = ldh4(Yn + d), yo = ldh4(Yn + 256 + d);                \
        const float4 yu = ldh4(Yn + 512 + d), yf = ldh4(Yn + 768 + d);          \
        const float4 gi = ldh4(Gi + d), go = ldh4(Gi + 256 + d);                \
        const float4 gu = ldh4(Gi + 512 + d);                                   \
        const float4 gl = ldh4(GfL), gr = ldh4(GfR);                            \
        const float4 cl = *(const float4*)(CL), cr = *(const float4*)(CR);      \
        _Pragma("unroll")                                                       \
        for (int t = 0; t < 4; t++) {                                           \
            const float fl = fsig((&gl.x)[t] + (&yf.x)[t]);                     \
            const float fr = fsig((&gr.x)[t] + (&yf.x)[t]);                     \
            co[t] = fsig((&yi.x)[t] + (&gi.x)[t]) *                             \
                        ftanh((&yu.x)[t] + (&gu.x)[t]) +                        \
                    fl * (&cl.x)[t] + fr * (&cr.x)[t];                          \
            ho[t] = fsig((&yo.x)[t] + (&go.x)[t]) * ftanh(co[t]);               \
        }                                                                       \
    }
    ELT(Y0, Gi0, Gf + d, Gf + 256 + d, cch + d, cch + 256 + d, c0, h0);
    ELT(Y1, Gi1, Gf + 512 + d, Gf + 768 + d, cch + 512 + d, cch + 768 + d,
        c1, h1);
#undef ELT

    const size_t b0 = (size_t)n0 * 256 + d;
    *(float4*)(g_c + b0) = make_float4(c0[0], c0[1], c0[2], c0[3]);
    *(float4*)(g_c + b0 + 256) = make_float4(c1[0], c1[1], c1[2], c1[3]);
    sth4(g_h + b0, h0[0], h0[1], h0[2], h0[3]);
    sth4(g_h + b0 + 256, h1[0], h1[1], h1[2], h1[3]);
    sth4(g_hs + (size_t)(pstart + j) * 256 + d,
         h0[0] + h1[0], h0[1] + h1[1], h0[2] + h1[2], h0[3] + h1[3]);
}

// Root (level 0): single node, writes the output.
__global__ void root_k(float* __restrict__ out) {
    const int d = (int)threadIdx.x;
    const float fx = __half2float(g_Y[768 + d]);
    const float fl = fsig(__half2float(g_Gf[d]) + fx);
    const float fr = fsig(__half2float(g_Gf[256 + d]) + fx);
    const float cl = g_c[256 + d];
    const float cr = g_c[512 + d];
    const float cv = fsig(__half2float(g_Y[d]) + __half2float(g_Giou[d])) *
                         ftanh(__half2float(g_Y[512 + d]) +
                               __half2float(g_Giou[512 + d])) +
                     fl * cl + fr * cr;
    const float hv = fsig(__half2float(g_Y[256 + d]) +
                          __half2float(g_Giou[256 + d])) * ftanh(cv);
    out[d] = cv;
    out[256 + d] = hv;
}

// ---------------------------------------------------------------------------
extern "C" void kernel_launch(void* const* d_in, const int* in_sizes, int n_in,
                              void* d_out, int out_size) {
    const float* X      = (const float*)d_in[0];
    const float* W_ioux = (const float*)d_in[1];
    const float* b_ioux = (const float*)d_in[2];
    const float* W_iouh = (const float*)d_in[3];
    const float* b_iouh = (const float*)d_in[4];
    const float* W_fx   = (const float*)d_in[5];
    const float* b_fx   = (const float*)d_in[6];
    const float* W_fh   = (const float*)d_in[7];
    const float* b_fh   = (const float*)d_in[8];
    float* out = (float*)d_out;

    cudaFuncSetAttribute(gemm_init_k,
                         cudaFuncAttributeMaxDynamicSharedMemorySize, SMEM_BYTES);
    cudaFuncSetAttribute(gemm_rec_k,
                         cudaFuncAttributeMaxDynamicSharedMemorySize, SMEM_BYTES);

    pack_weights_k<<<1024, 256>>>(W_ioux, b_ioux, W_iouh, b_iouh,
                                  W_fx, b_fx, W_fh, b_fh);
    convert_x_k<<<32768, 256>>>(X);

    // Y = X @ W1^T + b1 ; fx slab (cols 768..1023) only for internal rows
    gemm_init_k<<<7168, 128, SMEM_BYTES>>>();

    // leaves (level 16)
    leaf_k<<<8192, 256>>>();

    for (int lvl = 15; lvl >= 1; lvl--) {
        const int c = 1 << lvl;
        const int start = c - 1;
        const int cs = 2 * c - 1;
        if (c > 1024) {
            const int tiles_f = (2 * c + 127) >> 7;
            const int tiles_i = (c + 127) >> 7;
            gemm_rec_k<<<tiles_f * 2 + tiles_i * 6, 128, SMEM_BYTES>>>(cs, start,
                                                                       c);
        } else {
            const int warps = ((2 * c + 15) >> 4) * 4 + ((c + 15) >> 4) * 12;
            gemm_small_k<<<(warps + 3) / 4, 128>>>(cs, start, c);
        }
        const int npairs = c / 2;
        combine_k<<<(npairs + 3) / 4, 256>>>(start, cs, (1 << (lvl - 1)) - 1,
                                             npairs);
    }
    // level 0 (root)
    gemm_small_k<<<4, 128>>>(1, 0, 1);
    root_k<<<1, 256>>>(out);
}

// round 17
// speedup vs baseline: 1.1207x; 1.1207x over previous
#include <cuda_runtime.h>
#include <cuda_fp16.h>
#include <math.h>
#include <stdint.h>

// ---------------------------------------------------------------------------
// ChildSumTreeLSTM, perfect binary tree N = 131071 = 2^17 - 1, dims 256/256.
//
//   Y[N,1024]   = X @ [W_ioux; W_fx]^T + folded biases          (HMMA, fp16 out)
//   per level:  Gf[2c,256]   = h_children @ W_fh^T              (HMMA, fp16 out)
//               Giou[c,768]  = (h_l + h_r) @ W_iouh^T           (HMMA, hsum)
//               combine -> c,h of parents (+ next level's hsum)
//
// Large levels (c >= 4096): frozen engine — CTA 128x128, 4 warps of 64x64,
// K-chunk 64, 3-stage cp.async, one barrier per chunk, B reg double-buffer.
// Small levels (c <= 2048): mini engine — CTA 32x128, 4 warps of 16x64,
// SAME pipeline structure (smem + ldmatrix), 1/4 the serial depth per CTA,
// 8x the CTAs -> fills the chip on latency-bound levels.
// mma.sync.m16n8k16 f16 -> fp32 accum, single-term f16 operands.
// ---------------------------------------------------------------------------

#define NN 131071

// ---------------- device scratch (no allocations allowed) ------------------
static __device__ __half g_Y[(size_t)131072 * 1024];
static __device__ __half g_Gf[(size_t)65536 * 256];
static __device__ __half g_Giou[(size_t)32768 * 768];
static __device__ float  g_c[(size_t)131072 * 256];
static __device__ __half g_h[(size_t)131072 * 256];
static __device__ __half g_hs[(size_t)65536 * 256];
static __device__ __half g_X[(size_t)131072 * 256];   // row NN stays 0
static __device__ __half g_W1[1024 * 256];
static __device__ __half g_W2[1024 * 256];
static __device__ float  g_b1[1024];

// ---------------- helpers ---------------------------------------------------
__device__ __forceinline__ float fsig(float x) {
    return __fdividef(1.0f, 1.0f + __expf(-x));
}
__device__ __forceinline__ float ftanh(float x) {
    x = fminf(fmaxf(x, -30.0f), 30.0f);
    const float e = __expf(2.0f * x);
    return __fdividef(e - 1.0f, e + 1.0f);
}

__device__ __forceinline__ uint32_t smem_u32(const void* p) {
    uint32_t a;
    asm("{ .reg .u64 t; cvta.to.shared.u64 t, %1; cvt.u32.u64 %0, t; }"
        : "=r"(a) : "l"(p));
    return a;
}

__device__ __forceinline__ void ldmatrix_x4(uint32_t* r, uint32_t addr) {
    asm volatile("ldmatrix.sync.aligned.m8n8.x4.shared.b16 {%0,%1,%2,%3}, [%4];"
                 : "=r"(r[0]), "=r"(r[1]), "=r"(r[2]), "=r"(r[3]) : "r"(addr));
}

__device__ __forceinline__ void mma16816(float* d, const uint32_t* a,
                                         uint32_t b0, uint32_t b1) {
    asm volatile(
        "mma.sync.aligned.m16n8k16.row.col.f32.f16.f16.f32 "
        "{%0,%1,%2,%3}, {%4,%5,%6,%7}, {%8,%9}, {%0,%1,%2,%3};"
        : "+f"(d[0]), "+f"(d[1]), "+f"(d[2]), "+f"(d[3])
        : "r"(a[0]), "r"(a[1]), "r"(a[2]), "r"(a[3]), "r"(b0), "r"(b1));
}

__device__ __forceinline__ void cp16(uint32_t dst, const void* src) {
    asm volatile("cp.async.cg.shared.global [%0], [%1], 16;"
                 :: "r"(dst), "l"(__cvta_generic_to_global(src)));
}
#define CP_COMMIT() asm volatile("cp.async.commit_group;" ::: "memory")
#define CP_WAIT2()  asm volatile("cp.async.wait_group 2;" ::: "memory")

__device__ __forceinline__ uint32_t pack2(float x, float y) {
    __half2 h = __floats2half2_rn(x, y);
    return *reinterpret_cast<uint32_t*>(&h);
}
__device__ __forceinline__ float4 h4f(uint2 u) {
    __half2 a = *reinterpret_cast<__half2*>(&u.x);
    __half2 b = *reinterpret_cast<__half2*>(&u.y);
    float2 f0 = __half22float2(a), f1 = __half22float2(b);
    return make_float4(f0.x, f0.y, f1.x, f1.y);
}
__device__ __forceinline__ float4 ldh4(const __half* p) {
    return h4f(*reinterpret_cast<const uint2*>(p));
}
__device__ __forceinline__ void sth4(__half* p, float a, float b, float c, float d) {
    uint2 u;
    u.x = pack2(a, b);
    u.y = pack2(c, d);
    *reinterpret_cast<uint2*>(p) = u;
}

// ---------------- GEMM tile config (large-level engine) ----------------------
#define PSTRIDE 144
#define PANEL   (128 * PSTRIDE)    // 18432
#define STAGE   (2 * PANEL)        // 36864: A | B
#define SMEM_BYTES (3 * STAGE)     // 110592 -> 2 CTAs/SM

// Pointers pre-offset to tile. Row stride A/B = 256. Padded arrays: no guards.
// C is fp16, leading dim ldc. 128 threads: 4 warps, each a 64x64 subtile.
__device__ __forceinline__ void gemm_tile(const __half* __restrict__ A,
                                          const __half* __restrict__ B,
                                          __half* __restrict__ C, int ldc,
                                          const float* __restrict__ bias) {
    extern __shared__ char smem[];
    const uint32_t sb = smem_u32(smem);
    const int tid = (int)threadIdx.x;
    const int lane = tid & 31;
    const int wid = tid >> 5;        // 0..3
    const int wm = wid & 1;          // 64-row half
    const int wn = wid >> 1;         // 64-col half

    float acc[4][8][4];
#pragma unroll
    for (int mt = 0; mt < 4; mt++)
#pragma unroll
        for (int nt = 0; nt < 8; nt++)
#pragma unroll
            for (int i = 0; i < 4; i++) acc[mt][nt][i] = 0.0f;

    const __half* srcp[2] = {A, B};

    auto issue = [&](int kc) {
        const uint32_t sbase = sb + (uint32_t)(kc % 3) * STAGE;
        const int koff = kc * 64;
#pragma unroll
        for (int it = 0; it < 16; it++) {
            const int panel = it >> 3;               // 0: A, 1: B
            const int slot = (it & 7) * 128 + tid;   // 0..1023
            const int row = slot >> 3;
            const int c16 = slot & 7;
            cp16(sbase + (uint32_t)(panel * PANEL + row * PSTRIDE + c16 * 16),
                 srcp[panel] + (size_t)row * 256 + koff + c16 * 8);
        }
        CP_COMMIT();
    };

    issue(0);
    issue(1);
    issue(2);

    const uint32_t aoff =
        (uint32_t)((wm * 64 + (lane & 15)) * PSTRIDE + (lane >> 4) * 16);
    const uint32_t boff = (uint32_t)PANEL +
        (uint32_t)((wn * 64 + (lane & 15)) * PSTRIDE + (lane >> 4) * 16);

#pragma unroll 1
    for (int kc = 0; kc < 4; kc++) {
        CP_WAIT2();
        __syncthreads();   // single barrier per chunk (3-stage ring is safe)
        const uint32_t sbase = sb + (uint32_t)(kc % 3) * STAGE;
        const uint32_t arow = sbase + aoff;
        const uint32_t brow = sbase + boff;

        // B double-buffered across ks; A loaded at use.
        uint32_t bh[2][4][4];
#pragma unroll
        for (int nq = 0; nq < 4; nq++)
            ldmatrix_x4(bh[0][nq], brow + nq * (16 * PSTRIDE));

#pragma unroll
        for (int ks = 0; ks < 4; ks++) {
            const int cur = ks & 1;
            const int nxt = cur ^ 1;
            const uint32_t kb = (uint32_t)(ks * 32);
            uint32_t ah[4][4];
#pragma unroll
            for (int mt = 0; mt < 4; mt++)
                ldmatrix_x4(ah[mt], arow + mt * (16 * PSTRIDE) + kb);
            if (ks < 3) {
#pragma unroll
                for (int nq = 0; nq < 4; nq++)
                    ldmatrix_x4(bh[nxt][nq],
                                brow + nq * (16 * PSTRIDE) + kb + 32);
            }
#pragma unroll
            for (int mt = 0; mt < 4; mt++) {
#pragma unroll
                for (int nt = 0; nt < 8; nt++) {
                    mma16816(acc[mt][nt], ah[mt],
                             bh[cur][nt >> 1][nt & 1],
                             bh[cur][nt >> 1][(nt & 1) + 2]);
                }
            }
        }
        if (kc == 0) issue(3);
        CP_COMMIT();   // empty for kc>=1: keeps wait_group 2 uniform
    }

    // ---- epilogue: fp16 C, 2 cols per 32-bit store ----
#pragma unroll
    for (int mt = 0; mt < 4; mt++) {
        const int r0 = wm * 64 + mt * 16 + (lane >> 2);
#pragma unroll
        for (int nt = 0; nt < 8; nt++) {
            const int col = wn * 64 + nt * 8 + (lane & 3) * 2;
            float b0 = 0.f, b1 = 0.f;
            if (bias) { b0 = bias[col]; b1 = bias[col + 1]; }
            *reinterpret_cast<uint32_t*>(C + (size_t)r0 * ldc + col) =
                pack2(acc[mt][nt][0] + b0, acc[mt][nt][1] + b1);
            *reinterpret_cast<uint32_t*>(C + (size_t)(r0 + 8) * ldc + col) =
                pack2(acc[mt][nt][2] + b0, acc[mt][nt][3] + b1);
        }
    }
}

// ---------------- Mini engine: CTA 32x128, 4 warps of 16x64 ------------------
// Same pipeline: K-chunk 64, 3 stages, one barrier per chunk. For small levels.
#define APANEL_S (32 * PSTRIDE)            // 4608
#define BPANEL_S (128 * PSTRIDE)           // 18432
#define STAGE_S  (APANEL_S + BPANEL_S)     // 23040
#define SMEM_S   (3 * STAGE_S)             // 69120 -> 3 CTAs/SM

__device__ __forceinline__ void gemm_tile_mini(const __half* __restrict__ A,
                                               const __half* __restrict__ B,
                                               __half* __restrict__ C, int ldc) {
    extern __shared__ char smem[];
    const uint32_t sb = smem_u32(smem);
    const int tid = (int)threadIdx.x;
    const int lane = tid & 31;
    const int wid = tid >> 5;        // 0..3
    const int wm = wid & 1;          // 16-row half
    const int wn = wid >> 1;         // 64-col half

    float acc[8][4];
#pragma unroll
    for (int nt = 0; nt < 8; nt++)
#pragma unroll
        for (int i = 0; i < 4; i++) acc[nt][i] = 0.0f;

    auto issue = [&](int kc) {
        const uint32_t sbase = sb + (uint32_t)(kc % 3) * STAGE_S;
        const int koff = kc * 64;
        // 1280 16B-slots total: A 256 (32 rows x 8), B 1024 (128 rows x 8)
#pragma unroll
        for (int it = 0; it < 10; it++) {
            const int slot = it * 128 + tid;
            if (slot < 256) {
                const int row = slot >> 3;
                const int c16 = slot & 7;
                cp16(sbase + (uint32_t)(row * PSTRIDE + c16 * 16),
                     A + (size_t)row * 256 + koff + c16 * 8);
            } else {
                const int s2 = slot - 256;
                const int row = s2 >> 3;
                const int c16 = s2 & 7;
                cp16(sbase + (uint32_t)(APANEL_S + row * PSTRIDE + c16 * 16),
                     B + (size_t)row * 256 + koff + c16 * 8);
            }
        }
        CP_COMMIT();
    };

    issue(0);
    issue(1);
    issue(2);

    const uint32_t aoff =
        (uint32_t)((wm * 16 + (lane & 15)) * PSTRIDE + (lane >> 4) * 16);
    const uint32_t boff = (uint32_t)APANEL_S +
        (uint32_t)((wn * 64 + (lane & 15)) * PSTRIDE + (lane >> 4) * 16);

#pragma unroll 1
    for (int kc = 0; kc < 4; kc++) {
        CP_WAIT2();
        __syncthreads();
        const uint32_t arow = sb + (uint32_t)(kc % 3) * STAGE_S + aoff;
        const uint32_t brow = sb + (uint32_t)(kc % 3) * STAGE_S + boff;

#pragma unroll
        for (int ks = 0; ks < 4; ks++) {
            const uint32_t kb = (uint32_t)(ks * 32);
            uint32_t ah[4], bh[4][4];
            ldmatrix_x4(ah, arow + kb);
#pragma unroll
            for (int nq = 0; nq < 4; nq++)
                ldmatrix_x4(bh[nq], brow + nq * (16 * PSTRIDE) + kb);
#pragma unroll
            for (int nt = 0; nt < 8; nt++) {
                mma16816(acc[nt], ah,
                         bh[nt >> 1][nt & 1], bh[nt >> 1][(nt & 1) + 2]);
            }
        }
        if (kc == 0) issue(3);
        CP_COMMIT();   // empty for kc>=1
    }

    // epilogue: 16x64 per warp
#pragma unroll
    for (int nt = 0; nt < 8; nt++) {
        const int r0 = wm * 16 + (lane >> 2);
        const int col = wn * 64 + nt * 8 + (lane & 3) * 2;
        *reinterpret_cast<uint32_t*>(C + (size_t)r0 * ldc + col) =
            pack2(acc[nt][0], acc[nt][1]);
        *reinterpret_cast<uint32_t*>(C + (size_t)(r0 + 8) * ldc + col) =
            pack2(acc[nt][2], acc[nt][3]);
    }
}

// ---------------------------------------------------------------------------
// Init GEMM: single launch. Tiles 0..6143 = main slabs (1024 m x 6 n),
// tiles 6144..7167 = fx slab (first 512 m-tiles x 2 n).
__global__ void __launch_bounds__(128, 2) gemm_init_k() {
    const int bid = (int)blockIdx.x;
    size_t m0, n0;
    if (bid < 6144) {
        m0 = (size_t)(bid % 1024) * 128;
        n0 = (size_t)(bid / 1024) * 128;
    } else {
        const int r = bid - 6144;
        m0 = (size_t)(r % 512) * 128;
        n0 = (size_t)(6 + r / 512) * 128;
    }
    gemm_tile(g_X + m0 * 256, g_W1 + n0 * 256,
              g_Y + m0 * 1024 + n0, 1024, g_b1 + n0);
}

// Large-level recurrent GEMM (c >= 4096): tile-parallel grid.
__global__ void __launch_bounds__(128, 2) gemm_rec_k(int cs, int start, int c) {
    const int tiles_f = (2 * c + 127) >> 7;
    const int bid = (int)blockIdx.x;
    if (bid < tiles_f * 2) {
        const size_t mt = (size_t)(bid >> 1);
        const size_t nt = (size_t)(bid & 1);
        gemm_tile(g_h + ((size_t)cs + mt * 128) * 256,
                  g_W2 + (768 + nt * 128) * 256,
                  g_Gf + mt * 128 * 256 + nt * 128, 256, nullptr);
    } else {
        const int r = bid - tiles_f * 2;
        const size_t mt = (size_t)(r / 6);
        const size_t nt = (size_t)(r % 6);
        gemm_tile(g_hs + ((size_t)start + mt * 128) * 256,
                  g_W2 + nt * 128 * 256,
                  g_Giou + mt * 128 * 768 + nt * 128, 768, nullptr);
    }
}

// Small-level recurrent GEMM (c <= 2048): mini tiles, 32 rows each.
__global__ void __launch_bounds__(128) gemm_rec_mini_k(int cs, int start, int c) {
    const int tiles_f = (2 * c + 31) >> 5;
    const int bid = (int)blockIdx.x;
    if (bid < tiles_f * 2) {
        const size_t mt = (size_t)(bid >> 1);
        const size_t nt = (size_t)(bid & 1);
        gemm_tile_mini(g_h + ((size_t)cs + mt * 32) * 256,
                       g_W2 + (768 + nt * 128) * 256,
                       g_Gf + mt * 32 * 256 + nt * 128, 256);
    } else {
        const int r = bid - tiles_f * 2;
        const size_t mt = (size_t)(r / 6);
        const size_t nt = (size_t)(r % 6);
        gemm_tile_mini(g_hs + ((size_t)start + mt * 32) * 256,
                       g_W2 + nt * 128 * 256,
                       g_Giou + mt * 32 * 768 + nt * 128, 768);
    }
}

// ---------------------------------------------------------------------------
__global__ void pack_weights_k(const float* __restrict__ W_ioux,
                               const float* __restrict__ b_ioux,
                               const float* __restrict__ W_iouh,
                               const float* __restrict__ b_iouh,
                               const float* __restrict__ W_fx,
                               const float* __restrict__ b_fx,
                               const float* __restrict__ W_fh,
                               const float* __restrict__ b_fh) {
    const int i = blockIdx.x * blockDim.x + threadIdx.x;
    if (i >= 1024 * 256) return;
    const int r = i >> 8;
    const int cc = i & 255;
    const float w1 = (r < 768) ? W_ioux[i] : W_fx[(r - 768) * 256 + cc];
    const float w2 = (r < 768) ? W_iouh[i] : W_fh[(r - 768) * 256 + cc];
    g_W1[i] = __float2half_rn(w1);
    g_W2[i] = __float2half_rn(w2);
    if (cc == 0)
        g_b1[r] = (r < 768) ? (b_ioux[r] + b_iouh[r])
                            : (b_fx[r - 768] + b_fh[r - 768]);
}

__global__ void convert_x_k(const float* __restrict__ X) {
    const size_t i = ((size_t)blockIdx.x * 256 + threadIdx.x) * 4;
    if (i >= (size_t)NN * 256) return;
    const float4 v = *reinterpret_cast<const float4*>(X + i);
    sth4(g_X + i, v.x, v.y, v.z, v.w);
}

// ---------------------------------------------------------------------------
// Leaves (level 16): block = 4 sibling pairs x 64 lanes (4 elems per lane).
__global__ void leaf_k() {
    const int tid = (int)threadIdx.x;
    const int j = (int)blockIdx.x * 4 + (tid >> 6);   // pair id 0..32767
    const int d = (tid & 63) * 4;
    const int n0 = 65535 + 2 * j;
    const __half* Y0 = g_Y + (size_t)n0 * 1024;
    const __half* Y1 = Y0 + 1024;

    const float4 i0 = ldh4(Y0 + d),        i1 = ldh4(Y1 + d);
    const float4 o0 = ldh4(Y0 + 256 + d),  o1 = ldh4(Y1 + 256 + d);
    const float4 u0 = ldh4(Y0 + 512 + d),  u1 = ldh4(Y1 + 512 + d);

    float c0[4], h0[4], c1[4], h1[4];
#pragma unroll
    for (int t = 0; t < 4; t++) {
        c0[t] = fsig((&i0.x)[t]) * ftanh((&u0.x)[t]);
        h0[t] = fsig((&o0.x)[t]) * ftanh(c0[t]);
        c1[t] = fsig((&i1.x)[t]) * ftanh((&u1.x)[t]);
        h1[t] = fsig((&o1.x)[t]) * ftanh(c1[t]);
    }

    const size_t b0 = (size_t)n0 * 256 + d;
    *(float4*)(g_c + b0) = make_float4(c0[0], c0[1], c0[2], c0[3]);
    *(float4*)(g_c + b0 + 256) = make_float4(c1[0], c1[1], c1[2], c1[3]);
    sth4(g_h + b0, h0[0], h0[1], h0[2], h0[3]);
    sth4(g_h + b0 + 256, h1[0], h1[1], h1[2], h1[3]);
    sth4(g_hs + (size_t)(32767 + j) * 256 + d,
         h0[0] + h1[0], h0[1] + h1[1], h0[2] + h1[2], h0[3] + h1[3]);
}

// Internal levels lvl >= 1: block = 4 parent-pairs x 64 lanes.
__global__ void combine_k(int start, int cs, int pstart, int npairs) {
    const int tid = (int)threadIdx.x;
    const int j = (int)blockIdx.x * 4 + (tid >> 6);   // parent-pair id
    if (j >= npairs) return;
    const int d = (tid & 63) * 4;
    const int n0 = start + 2 * j;
    const __half* Y0 = g_Y + (size_t)n0 * 1024;
    const __half* Y1 = Y0 + 1024;
    const __half* Gi0 = g_Giou + (size_t)(2 * j) * 768;
    const __half* Gi1 = Gi0 + 768;
    const __half* Gf = g_Gf + (size_t)(4 * j) * 256;
    const float* cch = g_c + (size_t)(cs + 4 * j) * 256;

    float c0[4], h0[4], c1[4], h1[4];
#define ELT(Yn, Gi, GfL, GfR, CL, CR, co, ho)                                   \
    {                                                                           \
        const float4 yi = ldh4(Yn + d), yo = ldh4(Yn + 256 + d);                \
        const float4 yu = ldh4(Yn + 512 + d), yf = ldh4(Yn + 768 + d);          \
        const float4 gi = ldh4(Gi + d), go = ldh4(Gi + 256 + d);                \
        const float4 gu = ldh4(Gi + 512 + d);                                   \
        const float4 gl = ldh4(GfL), gr = ldh4(GfR);                            \
        const float4 cl = *(const float4*)(CL), cr = *(const float4*)(CR);      \
        _Pragma("unroll")                                                       \
        for (int t = 0; t < 4; t++) {                                           \
            const float fl = fsig((&gl.x)[t] + (&yf.x)[t]);                     \
            const float fr = fsig((&gr.x)[t] + (&yf.x)[t]);                     \
            co[t] = fsig((&yi.x)[t] + (&gi.x)[t]) *                             \
                        ftanh((&yu.x)[t] + (&gu.x)[t]) +                        \
                    fl * (&cl.x)[t] + fr * (&cr.x)[t];                          \
            ho[t] = fsig((&yo.x)[t] + (&go.x)[t]) * ftanh(co[t]);               \
        }                                                                       \
    }
    ELT(Y0, Gi0, Gf + d, Gf + 256 + d, cch + d, cch + 256 + d, c0, h0);
    ELT(Y1, Gi1, Gf + 512 + d, Gf + 768 + d, cch + 512 + d, cch + 768 + d,
        c1, h1);
#undef ELT

    const size_t b0 = (size_t)n0 * 256 + d;
    *(float4*)(g_c + b0) = make_float4(c0[0], c0[1], c0[2], c0[3]);
    *(float4*)(g_c + b0 + 256) = make_float4(c1[0], c1[1], c1[2], c1[3]);
    sth4(g_h + b0, h0[0], h0[1], h0[2], h0[3]);
    sth4(g_h + b0 + 256, h1[0], h1[1], h1[2], h1[3]);
    sth4(g_hs + (size_t)(pstart + j) * 256 + d,
         h0[0] + h1[0], h0[1] + h1[1], h0[2] + h1[2], h0[3] + h1[3]);
}

// Root (level 0): single node, writes the output.
__global__ void root_k(float* __restrict__ out) {
    const int d = (int)threadIdx.x;
    const float fx = __half2float(g_Y[768 + d]);
    const float fl = fsig(__half2float(g_Gf[d]) + fx);
    const float fr = fsig(__half2float(g_Gf[256 + d]) + fx);
    const float cl = g_c[256 + d];
    const float cr = g_c[512 + d];
    const float cv = fsig(__half2float(g_Y[d]) + __half2float(g_Giou[d])) *
                         ftanh(__half2float(g_Y[512 + d]) +
                               __half2float(g_Giou[512 + d])) +
                     fl * cl + fr * cr;
    const float hv = fsig(__half2float(g_Y[256 + d]) +
                          __half2float(g_Giou[256 + d])) * ftanh(cv);
    out[d] = cv;
    out[256 + d] = hv;
}

// ---------------------------------------------------------------------------
extern "C" void kernel_launch(void* const* d_in, const int* in_sizes, int n_in,
                              void* d_out, int out_size) {
    const float* X      = (const float*)d_in[0];
    const float* W_ioux = (const float*)d_in[1];
    const float* b_ioux = (const float*)d_in[2];
    const float* W_iouh = (const float*)d_in[3];
    const float* b_iouh = (const float*)d_in[4];
    const float* W_fx   = (const float*)d_in[5];
    const float* b_fx   = (const float*)d_in[6];
    const float* W_fh   = (const float*)d_in[7];
    const float* b_fh   = (const float*)d_in[8];
    float* out = (float*)d_out;

    cudaFuncSetAttribute(gemm_init_k,
                         cudaFuncAttributeMaxDynamicSharedMemorySize, SMEM_BYTES);
    cudaFuncSetAttribute(gemm_rec_k,
                         cudaFuncAttributeMaxDynamicSharedMemorySize, SMEM_BYTES);
    cudaFuncSetAttribute(gemm_rec_mini_k,
                         cudaFuncAttributeMaxDynamicSharedMemorySize, SMEM_S);

    pack_weights_k<<<1024, 256>>>(W_ioux, b_ioux, W_iouh, b_iouh,
                                  W_fx, b_fx, W_fh, b_fh);
    convert_x_k<<<32768, 256>>>(X);

    // Y = X @ W1^T + b1 ; fx slab (cols 768..1023) only for internal rows
    gemm_init_k<<<7168, 128, SMEM_BYTES>>>();

    // leaves (level 16)
    leaf_k<<<8192, 256>>>();

    for (int lvl = 15; lvl >= 1; lvl--) {
        const int c = 1 << lvl;
        const int start = c - 1;
        const int cs = 2 * c - 1;
        if (c >= 4096) {
            const int tiles_f = (2 * c + 127) >> 7;
            const int tiles_i = (c + 127) >> 7;
            gemm_rec_k<<<tiles_f * 2 + tiles_i * 6, 128, SMEM_BYTES>>>(cs, start,
                                                                       c);
        } else {
            const int tiles_f = (2 * c + 31) >> 5;
            const int tiles_i = (c + 31) >> 5;
            gemm_rec_mini_k<<<tiles_f * 2 + tiles_i * 6, 128, SMEM_S>>>(cs, start,
                                                                        c);
        }
        const int npairs = c / 2;
        combine_k<<<(npairs + 3) / 4, 256>>>(start, cs, (1 << (lvl - 1)) - 1,
                                             npairs);
    }
    // level 0 (root): c=1 -> tiles_f=1, tiles_i=1 -> 8 mini CTAs
    gemm_rec_mini_k<<<8, 128, SMEM_S>>>(1, 0, 1);
    root_k<<<1, 256>>>(out);
}